// round 5
// baseline (speedup 1.0000x reference)
#include <cuda_runtime.h>
#include <math_constants.h>

// Scratch (no device allocs allowed)
__device__ float g_map[32 * 2 * 64 * 64];   // [b][2][4096]
__device__ float g_scale[32 * 64 * 64];     // [b][4096]

#define NB 32
#define NC 256
#define HW 4096          // 64*64
#define HW4 1024         // HW / 4

// ---------------- Kernel 1: channel max + mean reduction ----------------
// Per chunk of 16 images: 512 blocks x 256 thr.
// Warp w reduces channels [32w,32w+32) for 32 float4 pixels.
__global__ __launch_bounds__(256) void reduce_kernel(const float* __restrict__ x, int b0) {
    int lane = threadIdx.x & 31;
    int wrp  = threadIdx.x >> 5;
    int g    = blockIdx.x;             // 0..511
    int b    = b0 + (g >> 5);
    int p4   = ((g & 31) << 5) + lane; // 0..1023

    const float4* __restrict__ xv = reinterpret_cast<const float4*>(x);
    size_t base = (size_t)b * (NC * HW4) + (size_t)(wrp << 5) * HW4 + p4;

    float4 mx = make_float4(-CUDART_INF_F, -CUDART_INF_F, -CUDART_INF_F, -CUDART_INF_F);
    float4 sm = make_float4(0.f, 0.f, 0.f, 0.f);

    #pragma unroll
    for (int c = 0; c < 32; c++) {
        float4 v = __ldg(&xv[base + (size_t)c * HW4]);
        mx.x = fmaxf(mx.x, v.x); mx.y = fmaxf(mx.y, v.y);
        mx.z = fmaxf(mx.z, v.z); mx.w = fmaxf(mx.w, v.w);
        sm.x += v.x; sm.y += v.y; sm.z += v.z; sm.w += v.w;
    }

    __shared__ float4 smax[8][32];
    __shared__ float4 ssum[8][32];
    smax[wrp][lane] = mx;
    ssum[wrp][lane] = sm;
    __syncthreads();

    if (wrp == 0) {
        float4 m = smax[0][lane];
        float4 s = ssum[0][lane];
        #pragma unroll
        for (int w = 1; w < 8; w++) {
            float4 m2 = smax[w][lane];
            float4 s2 = ssum[w][lane];
            m.x = fmaxf(m.x, m2.x); m.y = fmaxf(m.y, m2.y);
            m.z = fmaxf(m.z, m2.z); m.w = fmaxf(m.w, m2.w);
            s.x += s2.x; s.y += s2.y; s.z += s2.z; s.w += s2.w;
        }
        const float inv = 1.0f / (float)NC;
        s.x *= inv; s.y *= inv; s.z *= inv; s.w *= inv;

        float4* mv = reinterpret_cast<float4*>(g_map);
        mv[(size_t)b * 2048 + p4]        = m;
        mv[(size_t)b * 2048 + 1024 + p4] = s;
    }
}

// ---------------- Kernel 2: 7x7 conv (2ch -> 1) + sigmoid ----------------
// Per chunk: 16 images * 4096 pixels / 256 = 256 blocks.
__global__ __launch_bounds__(256) void conv_kernel(const float* __restrict__ w, int b0) {
    __shared__ float sw[98];
    if (threadIdx.x < 98) sw[threadIdx.x] = w[threadIdx.x];
    __syncthreads();

    int pid = blockIdx.x * blockDim.x + threadIdx.x;   // 0..65535 local
    int b  = b0 + (pid >> 12);
    int hw = pid & 4095;
    int h  = hw >> 6;
    int wc = hw & 63;

    const float* __restrict__ mp = g_map + (size_t)b * 2 * HW;

    float acc = 0.f;
    #pragma unroll
    for (int ky = 0; ky < 7; ky++) {
        int hy = h + ky - 3;
        if (hy < 0 || hy >= 64) continue;
        #pragma unroll
        for (int kx = 0; kx < 7; kx++) {
            int wx = wc + kx - 3;
            if (wx < 0 || wx >= 64) continue;
            int q = hy * 64 + wx;
            acc = fmaf(sw[ky * 7 + kx],      __ldg(&mp[q]),      acc);
            acc = fmaf(sw[49 + ky * 7 + kx], __ldg(&mp[HW + q]), acc);
        }
    }
    g_scale[(size_t)b * HW + hw] = 1.0f / (1.0f + __expf(-acc));
}

// ---------------- Kernel 3: out = x * scale ----------------
// Per chunk: 4096 blocks * 1024 float4. x reads are L2 hits (chunk was just
// read by K1 of this chunk and fits in L2); __ldcs marks last-use, __stcs
// streams the output past L2 so it never evicts x.
__global__ __launch_bounds__(256) void mul_kernel(const float* __restrict__ x,
                                                  float* __restrict__ out, int b0) {
    const float4* __restrict__ xv = reinterpret_cast<const float4*>(x);
    const float4* __restrict__ sv = reinterpret_cast<const float4*>(g_scale);
    float4* __restrict__ ov = reinterpret_cast<float4*>(out);

    size_t blk = (size_t)b0 * (NC * HW4) + (size_t)blockIdx.x * 1024;
    int b = (int)(blk >> 18);                     // constant per block

    float4 v[4], s[4];
    #pragma unroll
    for (int k = 0; k < 4; k++) {
        size_t i = blk + k * 256 + threadIdx.x;
        v[k] = __ldcs(&xv[i]);
        s[k] = __ldg(&sv[(size_t)b * HW4 + (i & 1023)]);
    }
    #pragma unroll
    for (int k = 0; k < 4; k++) {
        size_t i = blk + k * 256 + threadIdx.x;
        v[k].x *= s[k].x; v[k].y *= s[k].y; v[k].z *= s[k].z; v[k].w *= s[k].w;
        __stcs(&ov[i], v[k]);
    }
}

extern "C" void kernel_launch(void* const* d_in, const int* in_sizes, int n_in,
                              void* d_out, int out_size) {
    const float* x = (const float*)d_in[0];
    const float* w = (const float*)d_in[1];
    float* out = (float*)d_out;

    // 2 chunks of 16 images (67 MB each < 126 MB L2): K3 of a chunk re-reads
    // exactly the x range K1 of that chunk just cached.
    for (int b0 = 0; b0 < NB; b0 += 16) {
        reduce_kernel<<<512, 256>>>(x, b0);
        conv_kernel<<<256, 256>>>(w, b0);
        mul_kernel<<<4096, 256>>>(x, out, b0);
    }
}

// round 9
// speedup vs baseline: 1.0557x; 1.0557x over previous
#include <cuda_runtime.h>
#include <math_constants.h>

// Scratch (no device allocs allowed)
__device__ float g_map[32 * 2 * 64 * 64];   // [b][2][4096]
__device__ float g_scale[32 * 64 * 64];     // [b][4096]

#define NB 32
#define NC 256
#define HW 4096          // 64*64
#define HW4 1024         // HW / 4

// ---------------- Kernel 1: channel max + mean reduction ----------------
// 1024 blocks x 256 thr; warp w reduces channels [32w,32w+32) for 32 float4
// pixels. Explicit 8-wide load batches force MLP=8 per thread (ptxas at
// regs=32 was serializing into ~4-deep batches -> 75% DRAM; target 81%+).
__global__ __launch_bounds__(256) void reduce_kernel(const float* __restrict__ x) {
    int lane = threadIdx.x & 31;
    int wrp  = threadIdx.x >> 5;
    int g    = blockIdx.x;             // 0..1023
    int b    = g >> 5;
    int p4   = ((g & 31) << 5) + lane; // 0..1023

    const float4* __restrict__ xv = reinterpret_cast<const float4*>(x);
    size_t base = (size_t)b * (NC * HW4) + (size_t)(wrp << 5) * HW4 + p4;

    float4 mx = make_float4(-CUDART_INF_F, -CUDART_INF_F, -CUDART_INF_F, -CUDART_INF_F);
    float4 sm = make_float4(0.f, 0.f, 0.f, 0.f);

    #pragma unroll
    for (int cc = 0; cc < 32; cc += 8) {
        float4 v[8];
        #pragma unroll
        for (int j = 0; j < 8; j++)
            v[j] = __ldg(&xv[base + (size_t)(cc + j) * HW4]);
        #pragma unroll
        for (int j = 0; j < 8; j++) {
            mx.x = fmaxf(mx.x, v[j].x); mx.y = fmaxf(mx.y, v[j].y);
            mx.z = fmaxf(mx.z, v[j].z); mx.w = fmaxf(mx.w, v[j].w);
            sm.x += v[j].x; sm.y += v[j].y; sm.z += v[j].z; sm.w += v[j].w;
        }
    }

    __shared__ float4 smax[8][32];
    __shared__ float4 ssum[8][32];
    smax[wrp][lane] = mx;
    ssum[wrp][lane] = sm;
    __syncthreads();

    if (wrp == 0) {
        float4 m = smax[0][lane];
        float4 s = ssum[0][lane];
        #pragma unroll
        for (int w = 1; w < 8; w++) {
            float4 m2 = smax[w][lane];
            float4 s2 = ssum[w][lane];
            m.x = fmaxf(m.x, m2.x); m.y = fmaxf(m.y, m2.y);
            m.z = fmaxf(m.z, m2.z); m.w = fmaxf(m.w, m2.w);
            s.x += s2.x; s.y += s2.y; s.z += s2.z; s.w += s2.w;
        }
        const float inv = 1.0f / (float)NC;
        s.x *= inv; s.y *= inv; s.z *= inv; s.w *= inv;

        float4* mv = reinterpret_cast<float4*>(g_map);
        mv[(size_t)b * 2048 + p4]        = m;
        mv[(size_t)b * 2048 + 1024 + p4] = s;
    }
}

// ---------------- Kernel 2: 7x7 conv (2ch -> 1) + sigmoid ----------------
__global__ __launch_bounds__(256) void conv_kernel(const float* __restrict__ w) {
    __shared__ float sw[98];
    if (threadIdx.x < 98) sw[threadIdx.x] = w[threadIdx.x];
    __syncthreads();

    int pid = blockIdx.x * blockDim.x + threadIdx.x;
    int b  = pid >> 12;
    int hw = pid & 4095;
    int h  = hw >> 6;
    int wc = hw & 63;

    const float* __restrict__ mp = g_map + (size_t)b * 2 * HW;

    float acc = 0.f;
    #pragma unroll
    for (int ky = 0; ky < 7; ky++) {
        int hy = h + ky - 3;
        if (hy < 0 || hy >= 64) continue;
        #pragma unroll
        for (int kx = 0; kx < 7; kx++) {
            int wx = wc + kx - 3;
            if (wx < 0 || wx >= 64) continue;
            int q = hy * 64 + wx;
            acc = fmaf(sw[ky * 7 + kx],      __ldg(&mp[q]),      acc);
            acc = fmaf(sw[49 + ky * 7 + kx], __ldg(&mp[HW + q]), acc);
        }
    }
    g_scale[pid] = 1.0f / (1.0f + __expf(-acc));
}

// ---------------- Kernel 3: out = x * scale ----------------
// At the path-independent LTS cap (268MB @ ~6.45 TB/s); __ldcs/__stcs keep
// the working set from thrashing L2 but the cap itself is the limiter.
__global__ __launch_bounds__(256) void mul_kernel(const float* __restrict__ x,
                                                  float* __restrict__ out) {
    const float4* __restrict__ xv = reinterpret_cast<const float4*>(x);
    const float4* __restrict__ sv = reinterpret_cast<const float4*>(g_scale);
    float4* __restrict__ ov = reinterpret_cast<float4*>(out);

    size_t blk = (size_t)blockIdx.x * 1024;       // block covers 1024 float4
    int b = (int)(blk >> 18);                     // constant per block

    float4 v[4], s[4];
    #pragma unroll
    for (int k = 0; k < 4; k++) {
        size_t i = blk + k * 256 + threadIdx.x;
        v[k] = __ldcs(&xv[i]);
        s[k] = __ldg(&sv[(size_t)b * HW4 + (i & 1023)]);
    }
    #pragma unroll
    for (int k = 0; k < 4; k++) {
        size_t i = blk + k * 256 + threadIdx.x;
        v[k].x *= s[k].x; v[k].y *= s[k].y; v[k].z *= s[k].z; v[k].w *= s[k].w;
        __stcs(&ov[i], v[k]);
    }
}

extern "C" void kernel_launch(void* const* d_in, const int* in_sizes, int n_in,
                              void* d_out, int out_size) {
    const float* x = (const float*)d_in[0];
    const float* w = (const float*)d_in[1];
    float* out = (float*)d_out;

    reduce_kernel<<<1024, 256>>>(x);
    conv_kernel<<<131072 / 256, 256>>>(w);
    mul_kernel<<<8192, 256>>>(x, out);
}